// round 1
// baseline (speedup 1.0000x reference)
#include <cuda_runtime.h>
#include <cstdint>

#define NSP 4096      // H*W*D = 16^3
#define CCH 256
#define NHEADS 8
#define HD 32

// scratch (no cudaMalloc allowed)
__device__ float g_y[CCH * NSP];          // normalized conv output [C][N]
__device__ float g_qkv[3 * CCH * NSP];    // qkv [3C][N]
__device__ float g_att[CCH * NSP];        // attention output, channel-major [C][N]

// ---------------------------------------------------------------------------
// fast exp2 (Taylor degree-6 on fractional part), avoids MUFU bottleneck.
// valid for x <= 0 (softmax domain); clamped below -120.
// ---------------------------------------------------------------------------
__device__ __forceinline__ float exp2_poly(float x) {
    x = fmaxf(x, -120.0f);
    float fl = floorf(x);
    float f  = x - fl;                 // f in [0,1)
    float p  = 1.5403530e-4f;
    p = fmaf(p, f, 1.3333558e-3f);
    p = fmaf(p, f, 9.6181291e-3f);
    p = fmaf(p, f, 5.5504109e-2f);
    p = fmaf(p, f, 2.4022651e-1f);
    p = fmaf(p, f, 6.9314718e-1f);
    p = fmaf(p, f, 1.0f);
    int e = (int)fl;
    return p * __int_as_float((e + 127) << 23);
}

// ---------------------------------------------------------------------------
// Kernel 1: depthwise 3x3x3 conv + bias + InstanceNorm (per channel).
// One block per channel; 256 threads; channel slab (16KB) in smem.
// ---------------------------------------------------------------------------
__global__ __launch_bounds__(256) void conv_in_kernel(
    const float* __restrict__ x, const float* __restrict__ wdw,
    const float* __restrict__ bdw, float* __restrict__ y)
{
    const int c   = blockIdx.x;
    const int tid = threadIdx.x;
    __shared__ float xs[NSP];
    __shared__ float red[512];

    const float4* xg  = (const float4*)(x + (size_t)c * NSP);
    float4* xs4 = (float4*)xs;
    #pragma unroll
    for (int i = 0; i < 4; ++i) xs4[tid + 256 * i] = xg[tid + 256 * i];

    float wr[27];
    #pragma unroll
    for (int i = 0; i < 27; ++i) wr[i] = wdw[c * 27 + i];
    const float bias = bdw[c];
    __syncthreads();

    const int w  = tid >> 4;    // 0..15
    const int dd = tid & 15;    // 0..15

    float out[16];
    float s = 0.f, s2 = 0.f;
    for (int hh = 0; hh < 16; ++hh) {
        float acc = bias;
        #pragma unroll
        for (int i = 0; i < 3; ++i) {
            int ih = hh + i - 1;
            if ((unsigned)ih < 16u) {
                #pragma unroll
                for (int j = 0; j < 3; ++j) {
                    int iw = w + j - 1;
                    if ((unsigned)iw < 16u) {
                        #pragma unroll
                        for (int k = 0; k < 3; ++k) {
                            int id = dd + k - 1;
                            if ((unsigned)id < 16u)
                                acc = fmaf(xs[ih * 256 + iw * 16 + id], wr[i * 9 + j * 3 + k], acc);
                        }
                    }
                }
            }
        }
        out[hh] = acc;
        s += acc;
        s2 = fmaf(acc, acc, s2);
    }

    red[tid] = s; red[256 + tid] = s2;
    __syncthreads();
    for (int st = 128; st > 0; st >>= 1) {
        if (tid < st) { red[tid] += red[tid + st]; red[256 + tid] += red[256 + tid + st]; }
        __syncthreads();
    }
    const float mean = red[0] * (1.0f / NSP);
    const float var  = red[256] * (1.0f / NSP) - mean * mean;
    const float rs   = rsqrtf(var + 1e-5f);

    float* yc = y + (size_t)c * NSP;
    for (int hh = 0; hh < 16; ++hh)
        yc[hh * 256 + tid] = (out[hh] - mean) * rs;
}

// ---------------------------------------------------------------------------
// Kernel 2/4: tiled SGEMM with row-bias.  C[M,N] = A[M,K]·B[K,N] + bias[m]
// 64x64 tile, BK=16, 256 threads, 4x4 per thread.
// ---------------------------------------------------------------------------
__global__ __launch_bounds__(256) void sgemm_bias(
    const float* __restrict__ A, const float* __restrict__ B,
    const float* __restrict__ bias, float* __restrict__ C,
    int M, int N, int K)
{
    __shared__ float As[16][65];
    __shared__ float Bs[16][64];

    const int bm  = blockIdx.y * 64;
    const int bn  = blockIdx.x * 64;
    const int tid = threadIdx.x;
    const int tx  = tid & 15;      // 0..15 -> 4 cols each
    const int ty  = tid >> 4;      // 0..15 -> 4 rows each

    float acc[4][4] = {};

    for (int k0 = 0; k0 < K; k0 += 16) {
        #pragma unroll
        for (int i = 0; i < 4; ++i) {
            int e = tid + 256 * i;
            int m = e >> 4, kk = e & 15;
            As[kk][m] = A[(size_t)(bm + m) * K + (k0 + kk)];
        }
        #pragma unroll
        for (int i = 0; i < 4; ++i) {
            int e = tid + 256 * i;
            int kk = e >> 6, j = e & 63;
            Bs[kk][j] = B[(size_t)(k0 + kk) * N + (bn + j)];
        }
        __syncthreads();

        #pragma unroll
        for (int kk = 0; kk < 16; ++kk) {
            float a[4], bb[4];
            #pragma unroll
            for (int i = 0; i < 4; ++i) a[i]  = As[kk][ty * 4 + i];
            #pragma unroll
            for (int j = 0; j < 4; ++j) bb[j] = Bs[kk][tx * 4 + j];
            #pragma unroll
            for (int i = 0; i < 4; ++i)
                #pragma unroll
                for (int j = 0; j < 4; ++j)
                    acc[i][j] = fmaf(a[i], bb[j], acc[i][j]);
        }
        __syncthreads();
    }

    #pragma unroll
    for (int i = 0; i < 4; ++i) {
        const int m = bm + ty * 4 + i;
        const float bv = bias[m];
        float4 r = make_float4(acc[i][0] + bv, acc[i][1] + bv, acc[i][2] + bv, acc[i][3] + bv);
        *(float4*)(C + (size_t)m * N + bn + tx * 4) = r;
    }
}

// ---------------------------------------------------------------------------
// Kernel 3: flash attention, fp32.
// grid (16, 8): 16 query blocks x 8 heads. 128 threads, 2 query rows/thread.
// smem K/V tiles of 64 keys stored as [d][j] (float4 over j).
// q pre-scaled by hd^-0.5 * log2(e); softmax in exp2 domain via poly.
// output written channel-major: g_att[(h*32+d)*N + n]  (== transpose(-1,-2))
// ---------------------------------------------------------------------------
__global__ __launch_bounds__(128) void attn_kernel(
    const float* __restrict__ qkv, float* __restrict__ out)
{
    const int h   = blockIdx.y;
    const int n0  = blockIdx.x * 256;
    const int tid = threadIdx.x;

    __shared__ float4 sK[32 * 16];   // [d][j/4]
    __shared__ float4 sV[32 * 16];

    const float scale2 = 0.17677669529663688f * 1.4426950408889634f; // hd^-0.5 * log2e

    const float* qb = qkv + (size_t)(h * HD) * NSP;
    const float* kb = qkv + (size_t)(CCH + h * HD) * NSP;
    const float* vb = qkv + (size_t)(2 * CCH + h * HD) * NSP;

    const int r0 = n0 + tid;
    const int r1 = n0 + tid + 128;

    float q[2][32], o[2][32];
    #pragma unroll
    for (int d = 0; d < 32; ++d) {
        q[0][d] = qb[d * NSP + r0] * scale2;
        q[1][d] = qb[d * NSP + r1] * scale2;
        o[0][d] = 0.f; o[1][d] = 0.f;
    }
    float m[2] = {-1e30f, -1e30f};
    float l[2] = {0.f, 0.f};

    for (int j0 = 0; j0 < NSP; j0 += 64) {
        #pragma unroll
        for (int i = 0; i < 4; ++i) {
            int e = tid + 128 * i;
            int d = e >> 4, jc = e & 15;
            sK[e] = *(const float4*)(kb + d * NSP + j0 + jc * 4);
            sV[e] = *(const float4*)(vb + d * NSP + j0 + jc * 4);
        }
        __syncthreads();

        #pragma unroll 1
        for (int jj = 0; jj < 16; ++jj) {
            float s[2][4];
            #pragma unroll
            for (int r = 0; r < 2; ++r)
                #pragma unroll
                for (int i = 0; i < 4; ++i) s[r][i] = 0.f;

            #pragma unroll
            for (int d = 0; d < 32; ++d) {
                float4 k4 = sK[(d << 4) + jj];
                s[0][0] = fmaf(q[0][d], k4.x, s[0][0]);
                s[0][1] = fmaf(q[0][d], k4.y, s[0][1]);
                s[0][2] = fmaf(q[0][d], k4.z, s[0][2]);
                s[0][3] = fmaf(q[0][d], k4.w, s[0][3]);
                s[1][0] = fmaf(q[1][d], k4.x, s[1][0]);
                s[1][1] = fmaf(q[1][d], k4.y, s[1][1]);
                s[1][2] = fmaf(q[1][d], k4.z, s[1][2]);
                s[1][3] = fmaf(q[1][d], k4.w, s[1][3]);
            }

            float p[2][4];
            #pragma unroll
            for (int r = 0; r < 2; ++r) {
                float mt = fmaxf(fmaxf(s[r][0], s[r][1]), fmaxf(s[r][2], s[r][3]));
                if (mt > m[r]) {
                    float al = exp2_poly(m[r] - mt);
                    l[r] *= al;
                    m[r] = mt;
                    #pragma unroll
                    for (int d = 0; d < 32; ++d) o[r][d] *= al;
                }
                p[r][0] = exp2_poly(s[r][0] - m[r]);
                p[r][1] = exp2_poly(s[r][1] - m[r]);
                p[r][2] = exp2_poly(s[r][2] - m[r]);
                p[r][3] = exp2_poly(s[r][3] - m[r]);
                l[r] += (p[r][0] + p[r][1]) + (p[r][2] + p[r][3]);
            }

            #pragma unroll
            for (int d = 0; d < 32; ++d) {
                float4 v4 = sV[(d << 4) + jj];
                #pragma unroll
                for (int r = 0; r < 2; ++r)
                    o[r][d] = fmaf(p[r][0], v4.x,
                               fmaf(p[r][1], v4.y,
                                fmaf(p[r][2], v4.z,
                                 fmaf(p[r][3], v4.w, o[r][d]))));
            }
        }
        __syncthreads();
    }

    const float inv0 = 1.0f / l[0];
    const float inv1 = 1.0f / l[1];
    float* ob = out + (size_t)(h * HD) * NSP;
    #pragma unroll
    for (int d = 0; d < 32; ++d) {
        ob[d * NSP + r0] = o[0][d] * inv0;
        ob[d * NSP + r1] = o[1][d] * inv1;
    }
}

// ---------------------------------------------------------------------------
extern "C" void kernel_launch(void* const* d_in, const int* in_sizes, int n_in,
                              void* d_out, int out_size)
{
    const float* x      = (const float*)d_in[0];
    const float* w_dw   = (const float*)d_in[1];
    const float* b_dw   = (const float*)d_in[2];
    const float* w_qkv  = (const float*)d_in[3];
    const float* b_qkv  = (const float*)d_in[4];
    const float* w_proj = (const float*)d_in[5];
    const float* b_proj = (const float*)d_in[6];
    float* outp = (float*)d_out;

    float *py, *pqkv, *patt;
    cudaGetSymbolAddress((void**)&py,   g_y);
    cudaGetSymbolAddress((void**)&pqkv, g_qkv);
    cudaGetSymbolAddress((void**)&patt, g_att);

    conv_in_kernel<<<CCH, 256>>>(x, w_dw, b_dw, py);
    sgemm_bias<<<dim3(NSP / 64, (3 * CCH) / 64), 256>>>(w_qkv, py, b_qkv, pqkv, 3 * CCH, NSP, CCH);
    attn_kernel<<<dim3(16, NHEADS), 128>>>(pqkv, patt);
    sgemm_bias<<<dim3(NSP / 64, CCH / 64), 256>>>(w_proj, patt, b_proj, outp, CCH, NSP, CCH);
}

// round 3
// speedup vs baseline: 2.7274x; 2.7274x over previous
#include <cuda_runtime.h>
#include <cstdint>

#define NSP 4096      // H*W*D = 16^3
#define CCH 256
#define NHEADS 8
#define HD 32
#define QB 128
#define KB 64

// scratch (no cudaMalloc allowed)
__device__ float g_y[CCH * NSP];          // normalized conv output [C][N]
__device__ float g_qkv[3 * CCH * NSP];    // qkv [3C][N]
__device__ float g_att[CCH * NSP];        // attention output, channel-major [C][N]

// ---------------------------------------------------------------------------
__device__ __forceinline__ uint32_t f2tf32(float f) {
    uint32_t r; asm("cvt.rna.tf32.f32 %0, %1;" : "=r"(r) : "f"(f)); return r;
}

__device__ __forceinline__ void mma16n8k8(float c[4], const uint32_t a[4],
                                          uint32_t b0, uint32_t b1) {
    asm("mma.sync.aligned.m16n8k8.row.col.f32.tf32.tf32.f32 "
        "{%0,%1,%2,%3}, {%4,%5,%6,%7}, {%8,%9}, {%0,%1,%2,%3};"
        : "+f"(c[0]), "+f"(c[1]), "+f"(c[2]), "+f"(c[3])
        : "r"(a[0]), "r"(a[1]), "r"(a[2]), "r"(a[3]), "r"(b0), "r"(b1));
}

// fast exp2 (magic-number range reduction + degree-4 poly); valid |s| < 2^21
__device__ __forceinline__ float exp2m(float s, float& l) {
    float z = s + 12582912.0f;            // 1.5*2^23
    float f = s - (z - 12582912.0f);      // f in [-0.5, 0.5]
    int   e = __float_as_int(z) << 23;
    float p = 9.6181291e-3f;
    p = fmaf(p, f, 5.5504109e-2f);
    p = fmaf(p, f, 2.4022651e-1f);
    p = fmaf(p, f, 6.9314718e-1f);
    p = fmaf(p, f, 1.0f);
    float r = __int_as_float(__float_as_int(p) + e);
    l += r;
    return r;
}

// ---------------------------------------------------------------------------
// Kernel 1: depthwise 3x3x3 conv + bias + InstanceNorm (per channel).
// ---------------------------------------------------------------------------
__global__ __launch_bounds__(256) void conv_in_kernel(
    const float* __restrict__ x, const float* __restrict__ wdw,
    const float* __restrict__ bdw, float* __restrict__ y)
{
    const int c   = blockIdx.x;
    const int tid = threadIdx.x;
    __shared__ float xs[NSP];
    __shared__ float red[512];

    const float4* xg  = (const float4*)(x + (size_t)c * NSP);
    float4* xs4 = (float4*)xs;
    #pragma unroll
    for (int i = 0; i < 4; ++i) xs4[tid + 256 * i] = xg[tid + 256 * i];

    float wr[27];
    #pragma unroll
    for (int i = 0; i < 27; ++i) wr[i] = wdw[c * 27 + i];
    const float bias = bdw[c];
    __syncthreads();

    const int w  = tid >> 4;
    const int dd = tid & 15;

    float out[16];
    float s = 0.f, s2 = 0.f;
    for (int hh = 0; hh < 16; ++hh) {
        float acc = bias;
        #pragma unroll
        for (int i = 0; i < 3; ++i) {
            int ih = hh + i - 1;
            if ((unsigned)ih < 16u) {
                #pragma unroll
                for (int j = 0; j < 3; ++j) {
                    int iw = w + j - 1;
                    if ((unsigned)iw < 16u) {
                        #pragma unroll
                        for (int k = 0; k < 3; ++k) {
                            int id = dd + k - 1;
                            if ((unsigned)id < 16u)
                                acc = fmaf(xs[ih * 256 + iw * 16 + id], wr[i * 9 + j * 3 + k], acc);
                        }
                    }
                }
            }
        }
        out[hh] = acc;
        s += acc;
        s2 = fmaf(acc, acc, s2);
    }

    red[tid] = s; red[256 + tid] = s2;
    __syncthreads();
    for (int st = 128; st > 0; st >>= 1) {
        if (tid < st) { red[tid] += red[tid + st]; red[256 + tid] += red[256 + tid + st]; }
        __syncthreads();
    }
    const float mean = red[0] * (1.0f / NSP);
    const float var  = red[256] * (1.0f / NSP) - mean * mean;
    const float rs   = rsqrtf(var + 1e-5f);

    float* yc = y + (size_t)c * NSP;
    for (int hh = 0; hh < 16; ++hh)
        yc[hh * 256 + tid] = (out[hh] - mean) * rs;
}

// ---------------------------------------------------------------------------
// Kernel 2/4: tiled SGEMM with row-bias.
// ---------------------------------------------------------------------------
__global__ __launch_bounds__(256) void sgemm_bias(
    const float* __restrict__ A, const float* __restrict__ B,
    const float* __restrict__ bias, float* __restrict__ C,
    int M, int N, int K)
{
    __shared__ float As[16][65];
    __shared__ float Bs[16][64];

    const int bm  = blockIdx.y * 64;
    const int bn  = blockIdx.x * 64;
    const int tid = threadIdx.x;
    const int tx  = tid & 15;
    const int ty  = tid >> 4;

    float acc[4][4] = {};

    for (int k0 = 0; k0 < K; k0 += 16) {
        #pragma unroll
        for (int i = 0; i < 4; ++i) {
            int e = tid + 256 * i;
            int m = e >> 4, kk = e & 15;
            As[kk][m] = A[(size_t)(bm + m) * K + (k0 + kk)];
        }
        #pragma unroll
        for (int i = 0; i < 4; ++i) {
            int e = tid + 256 * i;
            int kk = e >> 6, j = e & 63;
            Bs[kk][j] = B[(size_t)(k0 + kk) * N + (bn + j)];
        }
        __syncthreads();

        #pragma unroll
        for (int kk = 0; kk < 16; ++kk) {
            float a[4], bb[4];
            #pragma unroll
            for (int i = 0; i < 4; ++i) a[i]  = As[kk][ty * 4 + i];
            #pragma unroll
            for (int j = 0; j < 4; ++j) bb[j] = Bs[kk][tx * 4 + j];
            #pragma unroll
            for (int i = 0; i < 4; ++i)
                #pragma unroll
                for (int j = 0; j < 4; ++j)
                    acc[i][j] = fmaf(a[i], bb[j], acc[i][j]);
        }
        __syncthreads();
    }

    #pragma unroll
    for (int i = 0; i < 4; ++i) {
        const int m = bm + ty * 4 + i;
        const float bv = bias[m];
        float4 r = make_float4(acc[i][0] + bv, acc[i][1] + bv, acc[i][2] + bv, acc[i][3] + bv);
        *(float4*)(C + (size_t)m * N + bn + tx * 4) = r;
    }
}

// ---------------------------------------------------------------------------
// Kernel 3: tf32 mma.sync flash attention (no-rescale softmax).
// grid (32, 8): 32 query blocks of 128 x 8 heads. 4 warps, 32 query rows/warp
// (two m16 row-blocks sharing all B fragments). K/V smem as [dim][key] str 72.
// P staged per-warp in smem (stride 68) for C-frag -> A-frag conversion.
// Dynamic smem: K 9216B + V 9216B + P 4*32*68*4 = 34816B -> 53248B.
// ---------------------------------------------------------------------------
__global__ __launch_bounds__(128) void attn_mma(
    const float* __restrict__ qkv, float* __restrict__ out)
{
    extern __shared__ float dsm[];
    float* Ksm = dsm;              // [32][72]
    float* Vsm = dsm + 32 * 72;    // [32][72]
    float* Psm = dsm + 2 * 32 * 72;// [4][32][68]

    const int tid  = threadIdx.x;
    const int w    = tid >> 5;
    const int lane = tid & 31;
    const int gid  = lane >> 2;    // 0..7
    const int tig  = lane & 3;     // 0..3
    const int h    = blockIdx.y;
    const int n0   = blockIdx.x * QB;

    const float SC = 0.17677669529663688f * 1.4426950408889634f; // hd^-0.5 * log2e

    const float* qb = qkv + (size_t)(h * HD) * NSP;
    const float* kb = qkv + (size_t)(CCH + h * HD) * NSP;
    const float* vb = qkv + (size_t)(2 * CCH + h * HD) * NSP;

    // Q fragments: 2 row-blocks (u) x 4 k-steps x 4 regs
    uint32_t qa[2][4][4];
    #pragma unroll
    for (int u = 0; u < 2; ++u) {
        const int rl = n0 + w * 32 + u * 16 + gid;
        #pragma unroll
        for (int ks = 0; ks < 4; ++ks) {
            const int d0 = ks * 8 + tig;
            qa[u][ks][0] = f2tf32(qb[d0 * NSP + rl] * SC);
            qa[u][ks][1] = f2tf32(qb[d0 * NSP + rl + 8] * SC);
            qa[u][ks][2] = f2tf32(qb[(d0 + 4) * NSP + rl] * SC);
            qa[u][ks][3] = f2tf32(qb[(d0 + 4) * NSP + rl + 8] * SC);
        }
    }

    float o[2][4][4] = {};
    float l[2][2] = {};
    float* Pw = Psm + w * 32 * 68;

    const int ld = tid >> 2;            // 0..31 (dim row)
    const int lk = (tid & 3) * 16;      // key col base

    for (int j0 = 0; j0 < NSP; j0 += KB) {
        __syncthreads();
        // load K,V tiles as [dim][key], tf32-rounded, conflict-free float4 STS
        #pragma unroll
        for (int m = 0; m < 4; ++m) {
            float4 kf = *(const float4*)(kb + ld * NSP + j0 + lk + m * 4);
            float4 vf = *(const float4*)(vb + ld * NSP + j0 + lk + m * 4);
            float4 ko, vo;
            ko.x = __uint_as_float(f2tf32(kf.x)); ko.y = __uint_as_float(f2tf32(kf.y));
            ko.z = __uint_as_float(f2tf32(kf.z)); ko.w = __uint_as_float(f2tf32(kf.w));
            vo.x = __uint_as_float(f2tf32(vf.x)); vo.y = __uint_as_float(f2tf32(vf.y));
            vo.z = __uint_as_float(f2tf32(vf.z)); vo.w = __uint_as_float(f2tf32(vf.w));
            *(float4*)(Ksm + ld * 72 + lk + m * 4) = ko;
            *(float4*)(Vsm + ld * 72 + lk + m * 4) = vo;
        }
        __syncthreads();

        // S = Q @ K^T : 8 n-tiles x 4 k-steps, B frags shared across both u
        float s0[8][4], s1[8][4];
        #pragma unroll
        for (int nt = 0; nt < 8; ++nt) {
            #pragma unroll
            for (int r = 0; r < 4; ++r) { s0[nt][r] = 0.f; s1[nt][r] = 0.f; }
            #pragma unroll
            for (int ks = 0; ks < 4; ++ks) {
                uint32_t b0 = __float_as_uint(Ksm[(ks * 8 + tig) * 72 + nt * 8 + gid]);
                uint32_t b1 = __float_as_uint(Ksm[(ks * 8 + tig + 4) * 72 + nt * 8 + gid]);
                mma16n8k8(s0[nt], qa[0][ks], b0, b1);
                mma16n8k8(s1[nt], qa[1][ks], b0, b1);
            }
        }

        // softmax exp (log2 domain) + write P to per-warp smem (tf32-rounded)
        #pragma unroll
        for (int nt = 0; nt < 8; ++nt) {
            const int cb = nt * 8 + 2 * tig;
            {
                float p0 = exp2m(s0[nt][0], l[0][0]);
                float p1 = exp2m(s0[nt][1], l[0][0]);
                float p2 = exp2m(s0[nt][2], l[0][1]);
                float p3 = exp2m(s0[nt][3], l[0][1]);
                Pw[gid * 68 + cb]           = __uint_as_float(f2tf32(p0));
                Pw[gid * 68 + cb + 1]       = __uint_as_float(f2tf32(p1));
                Pw[(gid + 8) * 68 + cb]     = __uint_as_float(f2tf32(p2));
                Pw[(gid + 8) * 68 + cb + 1] = __uint_as_float(f2tf32(p3));
            }
            {
                float p0 = exp2m(s1[nt][0], l[1][0]);
                float p1 = exp2m(s1[nt][1], l[1][0]);
                float p2 = exp2m(s1[nt][2], l[1][1]);
                float p3 = exp2m(s1[nt][3], l[1][1]);
                Pw[(16 + gid) * 68 + cb]       = __uint_as_float(f2tf32(p0));
                Pw[(16 + gid) * 68 + cb + 1]   = __uint_as_float(f2tf32(p1));
                Pw[(24 + gid) * 68 + cb]       = __uint_as_float(f2tf32(p2));
                Pw[(24 + gid) * 68 + cb + 1]   = __uint_as_float(f2tf32(p3));
            }
        }
        __syncwarp();

        // O += P @ V : 8 k-steps x 4 n-tiles, B frags shared across both u
        #pragma unroll
        for (int ks = 0; ks < 8; ++ks) {
            uint32_t a0[4], a1[4];
            const int kc = ks * 8 + tig;
            a0[0] = __float_as_uint(Pw[gid * 68 + kc]);
            a0[1] = __float_as_uint(Pw[(gid + 8) * 68 + kc]);
            a0[2] = __float_as_uint(Pw[gid * 68 + kc + 4]);
            a0[3] = __float_as_uint(Pw[(gid + 8) * 68 + kc + 4]);
            a1[0] = __float_as_uint(Pw[(16 + gid) * 68 + kc]);
            a1[1] = __float_as_uint(Pw[(24 + gid) * 68 + kc]);
            a1[2] = __float_as_uint(Pw[(16 + gid) * 68 + kc + 4]);
            a1[3] = __float_as_uint(Pw[(24 + gid) * 68 + kc + 4]);
            #pragma unroll
            for (int nt = 0; nt < 4; ++nt) {
                uint32_t b0 = __float_as_uint(Vsm[(nt * 8 + gid) * 72 + ks * 8 + tig]);
                uint32_t b1 = __float_as_uint(Vsm[(nt * 8 + gid) * 72 + ks * 8 + tig + 4]);
                // note B[k][n] = V[key k][dim n] = Vsm[dim n][key k]
                mma16n8k8(o[0][nt], a0, b0, b1);
                mma16n8k8(o[1][nt], a1, b0, b1);
            }
        }
    }

    // reduce l across quad (threads sharing gid differ in tig = lanes ^1, ^2)
    #pragma unroll
    for (int u = 0; u < 2; ++u)
        #pragma unroll
        for (int v = 0; v < 2; ++v) {
            l[u][v] += __shfl_xor_sync(0xFFFFFFFFu, l[u][v], 1);
            l[u][v] += __shfl_xor_sync(0xFFFFFFFFu, l[u][v], 2);
        }
    const float il[2][2] = { {1.f / l[0][0], 1.f / l[0][1]},
                             {1.f / l[1][0], 1.f / l[1][1]} };

    // stage normalized O in Psm, then coalesced store channel-major
    __syncthreads();
    #pragma unroll
    for (int u = 0; u < 2; ++u)
        #pragma unroll
        for (int nt = 0; nt < 4; ++nt) {
            const int cb = nt * 8 + 2 * tig;
            Pw[(u * 16 + gid) * 68 + cb]         = o[u][nt][0] * il[u][0];
            Pw[(u * 16 + gid) * 68 + cb + 1]     = o[u][nt][1] * il[u][0];
            Pw[(u * 16 + gid + 8) * 68 + cb]     = o[u][nt][2] * il[u][1];
            Pw[(u * 16 + gid + 8) * 68 + cb + 1] = o[u][nt][3] * il[u][1];
        }
    __syncthreads();

    const float* Pr = Psm + (tid >> 5) * 32 * 68 + (tid & 31) * 68;
    float* ob = out + (size_t)(h * HD) * NSP + n0 + tid;
    #pragma unroll
    for (int d = 0; d < 32; ++d)
        ob[(size_t)d * NSP] = Pr[d];
}

// ---------------------------------------------------------------------------
extern "C" void kernel_launch(void* const* d_in, const int* in_sizes, int n_in,
                              void* d_out, int out_size)
{
    const float* x      = (const float*)d_in[0];
    const float* w_dw   = (const float*)d_in[1];
    const float* b_dw   = (const float*)d_in[2];
    const float* w_qkv  = (const float*)d_in[3];
    const float* b_qkv  = (const float*)d_in[4];
    const float* w_proj = (const float*)d_in[5];
    const float* b_proj = (const float*)d_in[6];
    float* outp = (float*)d_out;

    float *py, *pqkv, *patt;
    cudaGetSymbolAddress((void**)&py,   g_y);
    cudaGetSymbolAddress((void**)&pqkv, g_qkv);
    cudaGetSymbolAddress((void**)&patt, g_att);

    static int smem_set = 0;
    const int ATTN_SMEM = (2 * 32 * 72 + 4 * 32 * 68) * 4;  // 53248 B
    if (!smem_set) {
        cudaFuncSetAttribute(attn_mma, cudaFuncAttributeMaxDynamicSharedMemorySize, ATTN_SMEM);
        smem_set = 1;
    }

    conv_in_kernel<<<CCH, 256>>>(x, w_dw, b_dw, py);
    sgemm_bias<<<dim3(NSP / 64, (3 * CCH) / 64), 256>>>(w_qkv, py, b_qkv, pqkv, 3 * CCH, NSP, CCH);
    attn_mma<<<dim3(NSP / QB, NHEADS), 128, ATTN_SMEM>>>(pqkv, patt);
    sgemm_bias<<<dim3(NSP / 64, CCH / 64), 256>>>(w_proj, patt, b_proj, outp, CCH, NSP, CCH);
}

// round 4
// speedup vs baseline: 3.0805x; 1.1295x over previous
#include <cuda_runtime.h>
#include <cstdint>

#define NSP 4096      // H*W*D = 16^3
#define CCH 256
#define NHEADS 8
#define HD 32
#define QB 128
#define KB 64

// scratch (no cudaMalloc allowed)
__device__ float g_y[CCH * NSP];          // normalized conv output [C][N]
__device__ float g_qkv[3 * CCH * NSP];    // qkv [3C][N]
__device__ float g_att[CCH * NSP];        // attention output, channel-major [C][N]

// ---------------------------------------------------------------------------
__device__ __forceinline__ uint32_t f2tf32(float f) {
    uint32_t r; asm("cvt.rna.tf32.f32 %0, %1;" : "=r"(r) : "f"(f)); return r;
}

__device__ __forceinline__ void mma16n8k8(float c[4], const uint32_t a[4],
                                          uint32_t b0, uint32_t b1) {
    asm("mma.sync.aligned.m16n8k8.row.col.f32.tf32.tf32.f32 "
        "{%0,%1,%2,%3}, {%4,%5,%6,%7}, {%8,%9}, {%0,%1,%2,%3};"
        : "+f"(c[0]), "+f"(c[1]), "+f"(c[2]), "+f"(c[3])
        : "r"(a[0]), "r"(a[1]), "r"(a[2]), "r"(a[3]), "r"(b0), "r"(b1));
}

// fast exp2 (magic-number range reduction + degree-4 poly); valid |s| < 2^21
__device__ __forceinline__ float exp2m(float s, float& l) {
    float z = s + 12582912.0f;            // 1.5*2^23
    float f = s - (z - 12582912.0f);      // f in [-0.5, 0.5]
    int   e = __float_as_int(z) << 23;
    float p = 9.6181291e-3f;
    p = fmaf(p, f, 5.5504109e-2f);
    p = fmaf(p, f, 2.4022651e-1f);
    p = fmaf(p, f, 6.9314718e-1f);
    p = fmaf(p, f, 1.0f);
    float r = __int_as_float(__float_as_int(p) + e);
    l += r;
    return r;
}

// ---------------------------------------------------------------------------
// Kernel 1: depthwise 3x3x3 conv + bias + InstanceNorm (per channel).
// ---------------------------------------------------------------------------
__global__ __launch_bounds__(256) void conv_in_kernel(
    const float* __restrict__ x, const float* __restrict__ wdw,
    const float* __restrict__ bdw, float* __restrict__ y)
{
    const int c   = blockIdx.x;
    const int tid = threadIdx.x;
    __shared__ float xs[NSP];
    __shared__ float red[512];

    const float4* xg  = (const float4*)(x + (size_t)c * NSP);
    float4* xs4 = (float4*)xs;
    #pragma unroll
    for (int i = 0; i < 4; ++i) xs4[tid + 256 * i] = xg[tid + 256 * i];

    float wr[27];
    #pragma unroll
    for (int i = 0; i < 27; ++i) wr[i] = wdw[c * 27 + i];
    const float bias = bdw[c];
    __syncthreads();

    const int w  = tid >> 4;
    const int dd = tid & 15;

    float out[16];
    float s = 0.f, s2 = 0.f;
    for (int hh = 0; hh < 16; ++hh) {
        float acc = bias;
        #pragma unroll
        for (int i = 0; i < 3; ++i) {
            int ih = hh + i - 1;
            if ((unsigned)ih < 16u) {
                #pragma unroll
                for (int j = 0; j < 3; ++j) {
                    int iw = w + j - 1;
                    if ((unsigned)iw < 16u) {
                        #pragma unroll
                        for (int k = 0; k < 3; ++k) {
                            int id = dd + k - 1;
                            if ((unsigned)id < 16u)
                                acc = fmaf(xs[ih * 256 + iw * 16 + id], wr[i * 9 + j * 3 + k], acc);
                        }
                    }
                }
            }
        }
        out[hh] = acc;
        s += acc;
        s2 = fmaf(acc, acc, s2);
    }

    red[tid] = s; red[256 + tid] = s2;
    __syncthreads();
    for (int st = 128; st > 0; st >>= 1) {
        if (tid < st) { red[tid] += red[tid + st]; red[256 + tid] += red[256 + tid + st]; }
        __syncthreads();
    }
    const float mean = red[0] * (1.0f / NSP);
    const float var  = red[256] * (1.0f / NSP) - mean * mean;
    const float rs   = rsqrtf(var + 1e-5f);

    float* yc = y + (size_t)c * NSP;
    for (int hh = 0; hh < 16; ++hh)
        yc[hh * 256 + tid] = (out[hh] - mean) * rs;
}

// ---------------------------------------------------------------------------
// Kernel 2/4: tf32 mma.sync GEMM with row-bias.
// C[M,N] = A[M,K]·B[K,N] + bias[m].  BM=128, BN=64, BK=32, 4 warps.
// Warp w: rows w*32..w*32+31 (2 m16 blocks), all 64 cols (8 n-tiles).
// As staged [k][m] stride 136, Bs [k][n] stride 72 (conflict-free frag reads).
// ---------------------------------------------------------------------------
__global__ __launch_bounds__(128) void gemm_tc(
    const float* __restrict__ A, const float* __restrict__ B,
    const float* __restrict__ bias, float* __restrict__ C,
    int M, int N, int K)
{
    __shared__ float As[32][136];
    __shared__ float Bs[32][72];

    const int tid  = threadIdx.x;
    const int w    = tid >> 5;
    const int lane = tid & 31;
    const int gid  = lane >> 2;
    const int tig  = lane & 3;
    const int bm   = blockIdx.y * 128;
    const int bn   = blockIdx.x * 64;

    float acc[2][8][4] = {};

    const int bkk = tid >> 2;          // 0..31 (B k-row)
    const int bnb = (tid & 3) * 16;    // B col base

    for (int k0 = 0; k0 < K; k0 += 32) {
        // A tile: thread = one m-row, transpose into As[k][m] (tf32-rounded)
        const float* ar = A + (size_t)(bm + tid) * K + k0;
        #pragma unroll
        for (int i = 0; i < 8; ++i) {
            float4 f = *(const float4*)(ar + i * 4);
            As[i * 4 + 0][tid] = __uint_as_float(f2tf32(f.x));
            As[i * 4 + 1][tid] = __uint_as_float(f2tf32(f.y));
            As[i * 4 + 2][tid] = __uint_as_float(f2tf32(f.z));
            As[i * 4 + 3][tid] = __uint_as_float(f2tf32(f.w));
        }
        // B tile: direct copy [k][n]
        const float* br = B + (size_t)(k0 + bkk) * N + bn + bnb;
        #pragma unroll
        for (int m2 = 0; m2 < 4; ++m2) {
            float4 f = *(const float4*)(br + m2 * 4);
            float4 o4;
            o4.x = __uint_as_float(f2tf32(f.x));
            o4.y = __uint_as_float(f2tf32(f.y));
            o4.z = __uint_as_float(f2tf32(f.z));
            o4.w = __uint_as_float(f2tf32(f.w));
            *(float4*)(&Bs[bkk][bnb + m2 * 4]) = o4;
        }
        __syncthreads();

        #pragma unroll
        for (int ks = 0; ks < 4; ++ks) {
            uint32_t a[2][4];
            #pragma unroll
            for (int u = 0; u < 2; ++u) {
                const int mb = w * 32 + u * 16 + gid;
                a[u][0] = __float_as_uint(As[ks * 8 + tig][mb]);
                a[u][1] = __float_as_uint(As[ks * 8 + tig][mb + 8]);
                a[u][2] = __float_as_uint(As[ks * 8 + tig + 4][mb]);
                a[u][3] = __float_as_uint(As[ks * 8 + tig + 4][mb + 8]);
            }
            #pragma unroll
            for (int nt = 0; nt < 8; ++nt) {
                uint32_t b0 = __float_as_uint(Bs[ks * 8 + tig][nt * 8 + gid]);
                uint32_t b1 = __float_as_uint(Bs[ks * 8 + tig + 4][nt * 8 + gid]);
                mma16n8k8(acc[0][nt], a[0], b0, b1);
                mma16n8k8(acc[1][nt], a[1], b0, b1);
            }
        }
        __syncthreads();
    }

    #pragma unroll
    for (int u = 0; u < 2; ++u) {
        const int m0 = bm + w * 32 + u * 16 + gid;
        const float bv0 = bias[m0];
        const float bv1 = bias[m0 + 8];
        #pragma unroll
        for (int nt = 0; nt < 8; ++nt) {
            const int n = bn + nt * 8 + tig * 2;
            float2 r0 = make_float2(acc[u][nt][0] + bv0, acc[u][nt][1] + bv0);
            float2 r1 = make_float2(acc[u][nt][2] + bv1, acc[u][nt][3] + bv1);
            *(float2*)(C + (size_t)m0 * N + n)       = r0;
            *(float2*)(C + (size_t)(m0 + 8) * N + n) = r1;
        }
    }
}

// ---------------------------------------------------------------------------
// Kernel 3: tf32 mma.sync flash attention (no-rescale softmax).
// grid (32, 8). 4 warps, 32 query rows/warp. K/V smem [dim][key] stride 72.
// P staged per-warp in smem (stride 68) for C-frag -> A-frag conversion.
// ---------------------------------------------------------------------------
__global__ __launch_bounds__(128) void attn_mma(
    const float* __restrict__ qkv, float* __restrict__ out)
{
    extern __shared__ float dsm[];
    float* Ksm = dsm;              // [32][72]
    float* Vsm = dsm + 32 * 72;    // [32][72]
    float* Psm = dsm + 2 * 32 * 72;// [4][32][68]

    const int tid  = threadIdx.x;
    const int w    = tid >> 5;
    const int lane = tid & 31;
    const int gid  = lane >> 2;
    const int tig  = lane & 3;
    const int h    = blockIdx.y;
    const int n0   = blockIdx.x * QB;

    const float SC = 0.17677669529663688f * 1.4426950408889634f; // hd^-0.5 * log2e

    const float* qb = qkv + (size_t)(h * HD) * NSP;
    const float* kb = qkv + (size_t)(CCH + h * HD) * NSP;
    const float* vb = qkv + (size_t)(2 * CCH + h * HD) * NSP;

    uint32_t qa[2][4][4];
    #pragma unroll
    for (int u = 0; u < 2; ++u) {
        const int rl = n0 + w * 32 + u * 16 + gid;
        #pragma unroll
        for (int ks = 0; ks < 4; ++ks) {
            const int d0 = ks * 8 + tig;
            qa[u][ks][0] = f2tf32(qb[d0 * NSP + rl] * SC);
            qa[u][ks][1] = f2tf32(qb[d0 * NSP + rl + 8] * SC);
            qa[u][ks][2] = f2tf32(qb[(d0 + 4) * NSP + rl] * SC);
            qa[u][ks][3] = f2tf32(qb[(d0 + 4) * NSP + rl + 8] * SC);
        }
    }

    float o[2][4][4] = {};
    float l[2][2] = {};
    float* Pw = Psm + w * 32 * 68;

    const int ld = tid >> 2;
    const int lk = (tid & 3) * 16;

    for (int j0 = 0; j0 < NSP; j0 += KB) {
        __syncthreads();
        #pragma unroll
        for (int m = 0; m < 4; ++m) {
            float4 kf = *(const float4*)(kb + ld * NSP + j0 + lk + m * 4);
            float4 vf = *(const float4*)(vb + ld * NSP + j0 + lk + m * 4);
            float4 ko, vo;
            ko.x = __uint_as_float(f2tf32(kf.x)); ko.y = __uint_as_float(f2tf32(kf.y));
            ko.z = __uint_as_float(f2tf32(kf.z)); ko.w = __uint_as_float(f2tf32(kf.w));
            vo.x = __uint_as_float(f2tf32(vf.x)); vo.y = __uint_as_float(f2tf32(vf.y));
            vo.z = __uint_as_float(f2tf32(vf.z)); vo.w = __uint_as_float(f2tf32(vf.w));
            *(float4*)(Ksm + ld * 72 + lk + m * 4) = ko;
            *(float4*)(Vsm + ld * 72 + lk + m * 4) = vo;
        }
        __syncthreads();

        float s0[8][4], s1[8][4];
        #pragma unroll
        for (int nt = 0; nt < 8; ++nt) {
            #pragma unroll
            for (int r = 0; r < 4; ++r) { s0[nt][r] = 0.f; s1[nt][r] = 0.f; }
            #pragma unroll
            for (int ks = 0; ks < 4; ++ks) {
                uint32_t b0 = __float_as_uint(Ksm[(ks * 8 + tig) * 72 + nt * 8 + gid]);
                uint32_t b1 = __float_as_uint(Ksm[(ks * 8 + tig + 4) * 72 + nt * 8 + gid]);
                mma16n8k8(s0[nt], qa[0][ks], b0, b1);
                mma16n8k8(s1[nt], qa[1][ks], b0, b1);
            }
        }

        #pragma unroll
        for (int nt = 0; nt < 8; ++nt) {
            const int cb = nt * 8 + 2 * tig;
            {
                float p0 = exp2m(s0[nt][0], l[0][0]);
                float p1 = exp2m(s0[nt][1], l[0][0]);
                float p2 = exp2m(s0[nt][2], l[0][1]);
                float p3 = exp2m(s0[nt][3], l[0][1]);
                Pw[gid * 68 + cb]           = __uint_as_float(f2tf32(p0));
                Pw[gid * 68 + cb + 1]       = __uint_as_float(f2tf32(p1));
                Pw[(gid + 8) * 68 + cb]     = __uint_as_float(f2tf32(p2));
                Pw[(gid + 8) * 68 + cb + 1] = __uint_as_float(f2tf32(p3));
            }
            {
                float p0 = exp2m(s1[nt][0], l[1][0]);
                float p1 = exp2m(s1[nt][1], l[1][0]);
                float p2 = exp2m(s1[nt][2], l[1][1]);
                float p3 = exp2m(s1[nt][3], l[1][1]);
                Pw[(16 + gid) * 68 + cb]       = __uint_as_float(f2tf32(p0));
                Pw[(16 + gid) * 68 + cb + 1]   = __uint_as_float(f2tf32(p1));
                Pw[(24 + gid) * 68 + cb]       = __uint_as_float(f2tf32(p2));
                Pw[(24 + gid) * 68 + cb + 1]   = __uint_as_float(f2tf32(p3));
            }
        }
        __syncwarp();

        #pragma unroll
        for (int ks = 0; ks < 8; ++ks) {
            uint32_t a0[4], a1[4];
            const int kc = ks * 8 + tig;
            a0[0] = __float_as_uint(Pw[gid * 68 + kc]);
            a0[1] = __float_as_uint(Pw[(gid + 8) * 68 + kc]);
            a0[2] = __float_as_uint(Pw[gid * 68 + kc + 4]);
            a0[3] = __float_as_uint(Pw[(gid + 8) * 68 + kc + 4]);
            a1[0] = __float_as_uint(Pw[(16 + gid) * 68 + kc]);
            a1[1] = __float_as_uint(Pw[(24 + gid) * 68 + kc]);
            a1[2] = __float_as_uint(Pw[(16 + gid) * 68 + kc + 4]);
            a1[3] = __float_as_uint(Pw[(24 + gid) * 68 + kc + 4]);
            #pragma unroll
            for (int nt = 0; nt < 4; ++nt) {
                uint32_t b0 = __float_as_uint(Vsm[(nt * 8 + gid) * 72 + ks * 8 + tig]);
                uint32_t b1 = __float_as_uint(Vsm[(nt * 8 + gid) * 72 + ks * 8 + tig + 4]);
                mma16n8k8(o[0][nt], a0, b0, b1);
                mma16n8k8(o[1][nt], a1, b0, b1);
            }
        }
    }

    #pragma unroll
    for (int u = 0; u < 2; ++u)
        #pragma unroll
        for (int v = 0; v < 2; ++v) {
            l[u][v] += __shfl_xor_sync(0xFFFFFFFFu, l[u][v], 1);
            l[u][v] += __shfl_xor_sync(0xFFFFFFFFu, l[u][v], 2);
        }
    const float il[2][2] = { {1.f / l[0][0], 1.f / l[0][1]},
                             {1.f / l[1][0], 1.f / l[1][1]} };

    __syncthreads();
    #pragma unroll
    for (int u = 0; u < 2; ++u)
        #pragma unroll
        for (int nt = 0; nt < 4; ++nt) {
            const int cb = nt * 8 + 2 * tig;
            Pw[(u * 16 + gid) * 68 + cb]         = o[u][nt][0] * il[u][0];
            Pw[(u * 16 + gid) * 68 + cb + 1]     = o[u][nt][1] * il[u][0];
            Pw[(u * 16 + gid + 8) * 68 + cb]     = o[u][nt][2] * il[u][1];
            Pw[(u * 16 + gid + 8) * 68 + cb + 1] = o[u][nt][3] * il[u][1];
        }
    __syncthreads();

    const float* Pr = Psm + (tid >> 5) * 32 * 68 + (tid & 31) * 68;
    float* ob = out + (size_t)(h * HD) * NSP + n0 + tid;
    #pragma unroll
    for (int d = 0; d < 32; ++d)
        ob[(size_t)d * NSP] = Pr[d];
}

// ---------------------------------------------------------------------------
extern "C" void kernel_launch(void* const* d_in, const int* in_sizes, int n_in,
                              void* d_out, int out_size)
{
    const float* x      = (const float*)d_in[0];
    const float* w_dw   = (const float*)d_in[1];
    const float* b_dw   = (const float*)d_in[2];
    const float* w_qkv  = (const float*)d_in[3];
    const float* b_qkv  = (const float*)d_in[4];
    const float* w_proj = (const float*)d_in[5];
    const float* b_proj = (const float*)d_in[6];
    float* outp = (float*)d_out;

    float *py, *pqkv, *patt;
    cudaGetSymbolAddress((void**)&py,   g_y);
    cudaGetSymbolAddress((void**)&pqkv, g_qkv);
    cudaGetSymbolAddress((void**)&patt, g_att);

    static int smem_set = 0;
    const int ATTN_SMEM = (2 * 32 * 72 + 4 * 32 * 68) * 4;  // 53248 B
    if (!smem_set) {
        cudaFuncSetAttribute(attn_mma, cudaFuncAttributeMaxDynamicSharedMemorySize, ATTN_SMEM);
        smem_set = 1;
    }

    conv_in_kernel<<<CCH, 256>>>(x, w_dw, b_dw, py);
    gemm_tc<<<dim3(NSP / 64, (3 * CCH) / 128), 128>>>(w_qkv, py, b_qkv, pqkv, 3 * CCH, NSP, CCH);
    attn_mma<<<dim3(NSP / QB, NHEADS), 128, ATTN_SMEM>>>(pqkv, patt);
    gemm_tc<<<dim3(NSP / 64, CCH / 128), 128>>>(w_proj, patt, b_proj, outp, CCH, NSP, CCH);
}